// round 14
// baseline (speedup 1.0000x reference)
#include <cuda_runtime.h>
#include <cuda_fp16.h>
#include <math.h>
#include <stdint.h>

#define BB 16
#define TT 128
#define HH 1024
#define EE 1024
#define VV 32000
#define KK 2048

// ---- K1 (HMMA LSTM halves) ----
#define K1_BLOCKS 256
#define K1_THREADS 256
// smem: x planes resident (converted once), reduce buffer, tokens
#define XHI_OFF  0          // 16*1032*2 = 33024
#define XLO_OFF  33024
#define RED_OFF  66048      // 8*16*17*4 = 8704
#define TOK_OFF  74752
#define K1_SMEM  74816

// ---- K2 (logits) ----
#define K2_ROWS   128
#define K2_BLOCKS (VV / K2_ROWS)     // 250
#define K2_THREADS 256
#define NCHUNK 16
#define TAU 0.05f
#define HPAD 1032
#define LPAD 17
#define H_OFF    0                   // 33024
#define LOG_OFF  33024               // 8704
#define THR_OFF  41728
#define CNT_OFF  41792
#define CAND_OFF 41808
#define K2_SMEM  42320

// -------- persistent scratch --------
__device__ float  g_h[2][BB * HH];
__device__ float  g_c[BB * HH];
__device__ __half g_h16[BB * HH];                       // hi plane of h
__device__ __half g_hlo[BB * HH];                       // lo plane of h
__device__ __align__(128) __half g_WF[(size_t)VV * HH]; // fragment-packed W_lin
__device__ __align__(128) __half g_WhiF[(size_t)4 * HH * KK]; // fragment-packed gate hi
__device__ __align__(128) __half g_WloF[(size_t)4 * HH * KK]; // fragment-packed gate lo
__device__ float  g_gH[K1_BLOCKS * 256];
__device__ float  g_pb[4 * HH];
__device__ unsigned long long g_amax[2][BB];
__device__ unsigned g_approx[2][BB];
__device__ float  g_pexp[TT][BB][K2_BLOCKS];

// ---------------- helpers ----------------
__device__ __forceinline__ unsigned ford(float f) {
    unsigned u = __float_as_uint(f);
    return (u & 0x80000000u) ? ~u : (u | 0x80000000u);
}
__device__ __forceinline__ float funord(unsigned v) {
    unsigned bits = (v & 0x80000000u) ? (v ^ 0x80000000u) : ~v;
    return __uint_as_float(bits);
}
__device__ __forceinline__ uint32_t smem_u32(const void* p) {
    uint32_t a;
    asm("{ .reg .u64 t; cvta.to.shared.u64 t, %1; cvt.u32.u64 %0, t; }" : "=r"(a) : "l"(p));
    return a;
}
__device__ __forceinline__ void mma16816(float* c, uint32_t a0, uint32_t a1,
                                         uint32_t a2, uint32_t a3,
                                         uint32_t b0, uint32_t b1) {
    asm volatile(
        "mma.sync.aligned.m16n8k16.row.col.f32.f16.f16.f32 "
        "{%0,%1,%2,%3}, {%4,%5,%6,%7}, {%8,%9}, {%0,%1,%2,%3};"
        : "+f"(c[0]), "+f"(c[1]), "+f"(c[2]), "+f"(c[3])
        : "r"(a0), "r"(a1), "r"(a2), "r"(a3), "r"(b0), "r"(b1));
}

// ---------------------------------------------------------------------
__global__ void k_init(const float* __restrict__ h0, const float* __restrict__ c0,
                       const float* __restrict__ bih, const float* __restrict__ bhh) {
    int i = blockIdx.x * blockDim.x + threadIdx.x;
    if (i < BB * HH) {
        float h = h0[i];
        g_h[0][i] = h;
        g_c[i]    = c0[i];
        __half hh = __float2half_rn(h);
        g_h16[i] = hh;
        g_hlo[i] = __float2half_rn(h - __half2float(hh));
    }
    if (i < BB) g_amax[0][i] = (unsigned long long)(~1u);   // SOS = 1
    if (i < 4 * HH) {
        int j = i >> 2, g = i & 3;
        int orig = g * HH + j;
        g_pb[i] = bih[orig] + bhh[orig];
    }
}

// W_lin fp32 -> fragment-packed fp16 (proven R13 layout)
__global__ void k_cvtF(const float* __restrict__ W) {
    unsigned u = blockIdx.x * 256 + threadIdx.x;   // < 4,096,000
    int blk = u >> 14;
    int rem = u & 16383;
    int c   = rem >> 10;
    int rem2 = rem & 1023;
    int ks  = rem2 >> 8;
    int tt  = rem2 & 255;
    int warp = tt >> 5, lane = tt & 31;
    int r = lane >> 2, q4 = lane & 3;
    int row0 = blk * 128 + warp * 16 + r;
    int k = c * 64 + ks * 16 + q4 * 2;
    const float* p0 = W + (size_t)row0 * HH + k;
    const float* p1 = W + (size_t)(row0 + 8) * HH + k;
    float2 xa = *(const float2*)p0;
    float2 xb = *(const float2*)p1;
    float2 xc = *(const float2*)(p0 + 8);
    float2 xd = *(const float2*)(p1 + 8);
    __half2 ha = __floats2half2_rn(xa.x, xa.y);
    __half2 hb = __floats2half2_rn(xb.x, xb.y);
    __half2 hc = __floats2half2_rn(xc.x, xc.y);
    __half2 hd = __floats2half2_rn(xd.x, xd.y);
    uint4 o;
    o.x = *(uint32_t*)&ha; o.y = *(uint32_t*)&hb;
    o.z = *(uint32_t*)&hc; o.w = *(uint32_t*)&hd;
    *(uint4*)((char*)g_WF + (size_t)u * 16) = o;
}

// Gate weights -> split fp16, fragment-packed:
// unit index u = ((blk*8 + c)*8 + w)*64 + s*32 + lane; 16 B per unit per plane.
// k = c*256 + w*32 + s*16 + q4*2 (global K in [0,2048)); rows = blk*16 + r, +8.
__device__ __forceinline__ float ld_gate(const float* Wih, const float* Whh, int nr, int k) {
    int j = nr >> 2, g = nr & 3;
    int orig = g * HH + j;
    return (k < HH) ? Wih[(size_t)orig * HH + k] : Whh[(size_t)orig * HH + (k - HH)];
}
__global__ void k_cvt2F(const float* __restrict__ Wih, const float* __restrict__ Whh) {
    unsigned u = blockIdx.x * 256 + threadIdx.x;   // < 1,048,576
    int blk = u >> 12;                 // 4096 units per block
    int rem = u & 4095;
    int c   = rem >> 9;                // 512 units per chunk
    int rem2 = rem & 511;
    int w   = rem2 >> 6;
    int rem3 = rem2 & 63;
    int s   = rem3 >> 5;
    int lane = rem3 & 31;
    int r = lane >> 2, q4 = lane & 3;
    int row0 = blk * 16 + r, row1 = row0 + 8;
    int k = c * 256 + w * 32 + s * 16 + q4 * 2;
    float v[8];
    v[0] = ld_gate(Wih, Whh, row0, k);     v[1] = ld_gate(Wih, Whh, row0, k + 1);
    v[2] = ld_gate(Wih, Whh, row1, k);     v[3] = ld_gate(Wih, Whh, row1, k + 1);
    v[4] = ld_gate(Wih, Whh, row0, k + 8); v[5] = ld_gate(Wih, Whh, row0, k + 9);
    v[6] = ld_gate(Wih, Whh, row1, k + 8); v[7] = ld_gate(Wih, Whh, row1, k + 9);
    __half hi[8], lo[8];
#pragma unroll
    for (int q = 0; q < 8; q++) {
        __half h = __float2half_rn(v[q]);
        hi[q] = h;
        lo[q] = __float2half_rn(v[q] - __half2float(h));
    }
    *(uint4*)((char*)g_WhiF + (size_t)u * 16) = *(uint4*)hi;
    *(uint4*)((char*)g_WloF + (size_t)u * 16) = *(uint4*)lo;
}

// ---------------------------------------------------------------------
// Shared K1 GEMM body: barrier-free mainloop, W fragments via LDG.128,
// x planes resident in smem. cbase selects K half (0 = emb, 4 = h).
// Returns acc via pointer; assumes x planes already populated + synced.
__device__ __forceinline__ void k1_mainloop(
    char* sm, int blkid, int warp, int lane, int cbase, float acc[2][4]) {
    const int r = lane >> 2, q4 = lane & 3;
    const __half* xhi = (const __half*)(sm + XHI_OFF);
    const __half* xlo = (const __half*)(sm + XLO_OFF);
    const size_t fbase = (((size_t)blkid * 8) * 512 + (size_t)warp * 64 + lane) * 16;
    const char* fhi = (const char*)g_WhiF + fbase;
    const char* flo = (const char*)g_WloF + fbase;

    uint4 wh[2][2], wl[2][2];
#pragma unroll
    for (int s = 0; s < 2; s++) {
        wh[0][s] = *(const uint4*)(fhi + (size_t)cbase * 8192 + s * 512);
        wl[0][s] = *(const uint4*)(flo + (size_t)cbase * 8192 + s * 512);
    }
#pragma unroll
    for (int c = 0; c < 4; c++) {
        int cb = c & 1, nb = cb ^ 1;
        if (c + 1 < 4) {
#pragma unroll
            for (int s = 0; s < 2; s++) {
                wh[nb][s] = *(const uint4*)(fhi + (size_t)(cbase + c + 1) * 8192 + s * 512);
                wl[nb][s] = *(const uint4*)(flo + (size_t)(cbase + c + 1) * 8192 + s * 512);
            }
        }
#pragma unroll
        for (int s = 0; s < 2; s++) {
            int kg = c * 256 + warp * 32 + s * 16 + q4 * 2;
#pragma unroll
            for (int nbi = 0; nbi < 2; nbi++) {
                const __half* bx = xhi + (nbi * 8 + r) * 1032;
                const __half* by = xlo + (nbi * 8 + r) * 1032;
                uint32_t bh0 = *(const uint32_t*)(bx + kg);
                uint32_t bh1 = *(const uint32_t*)(bx + kg + 8);
                uint32_t bl0 = *(const uint32_t*)(by + kg);
                uint32_t bl1 = *(const uint32_t*)(by + kg + 8);
                mma16816(acc[nbi], wh[cb][s].x, wh[cb][s].y, wh[cb][s].z, wh[cb][s].w, bh0, bh1);
                mma16816(acc[nbi], wh[cb][s].x, wh[cb][s].y, wh[cb][s].z, wh[cb][s].w, bl0, bl1);
                mma16816(acc[nbi], wl[cb][s].x, wl[cb][s].y, wl[cb][s].z, wl[cb][s].w, bh0, bh1);
            }
        }
    }
}

__device__ __forceinline__ void k1_reduce(char* sm, int tid, int warp, int lane,
                                          float acc[2][4]) {
    float* red = (float*)(sm + RED_OFF);
    const int r = lane >> 2, q4 = lane & 3;
#pragma unroll
    for (int nbi = 0; nbi < 2; nbi++) {
        int col = nbi * 8 + q4 * 2;
        red[warp * 272 + r * 17 + col]           = acc[nbi][0];
        red[warp * 272 + r * 17 + col + 1]       = acc[nbi][1];
        red[warp * 272 + (r + 8) * 17 + col]     = acc[nbi][2];
        red[warp * 272 + (r + 8) * 17 + col + 1] = acc[nbi][3];
    }
    __syncthreads();
}

// ---------------------------------------------------------------------
// k_gemmH: partial gates = Whh_split @ h_t; PDL, W-fragment prefetch in prelude.
__global__ void __launch_bounds__(K1_THREADS)
k_gemmH(int t) {
    extern __shared__ char sm[];
    const int tid = threadIdx.x, warp = tid >> 5, lane = tid & 31;

    // prelude: W fragments are h-independent — prefetch chunk 4 (regs survive sync)
    const size_t fbase = (((size_t)blockIdx.x * 8) * 512 + (size_t)warp * 64 + lane) * 16;
    uint4 pre_h0 = *(const uint4*)((const char*)g_WhiF + fbase + (size_t)4 * 8192);
    uint4 pre_l0 = *(const uint4*)((const char*)g_WloF + fbase + (size_t)4 * 8192);
    (void)pre_h0; (void)pre_l0;   // warm L1/L2; mainloop reloads (cheap L1 hit)
    cudaGridDependencySynchronize();
    cudaTriggerProgrammaticLaunchCompletion();

    // copy h planes into smem
    __half* xhi = (__half*)(sm + XHI_OFF);
    __half* xlo = (__half*)(sm + XLO_OFF);
#pragma unroll
    for (int q = 0; q < 8; q++) {
        int i = tid + q * 256;
        int b = i >> 7, k8 = i & 127;
        *(float4*)(xhi + b * 1032 + k8 * 8) = *(const float4*)(g_h16 + b * HH + k8 * 8);
        *(float4*)(xlo + b * 1032 + k8 * 8) = *(const float4*)(g_hlo + b * HH + k8 * 8);
    }
    __syncthreads();

    float acc[2][4] = {{0.f,0.f,0.f,0.f},{0.f,0.f,0.f,0.f}};
    k1_mainloop(sm, blockIdx.x, warp, lane, 4, acc);
    k1_reduce(sm, tid, warp, lane, acc);

    float* red = (float*)(sm + RED_OFF);
    if (tid < 64) {
        int u = tid >> 4, b = tid & 15;
#pragma unroll
        for (int g = 0; g < 4; g++) {
            int row = u * 4 + g;
            float s = 0.f;
#pragma unroll
            for (int w = 0; w < 8; w++) s += red[w * 272 + row * 17 + b];
            g_gH[blockIdx.x * 256 + row * 16 + b] = s;
        }
    }
}

// ---------------------------------------------------------------------
// k_lstmX: gates = Wih_split @ emb[tok] + g_gH + bias; pointwise (plain launch).
__global__ void __launch_bounds__(K1_THREADS)
k_lstmX(int t, const float* __restrict__ emb) {
    extern __shared__ char sm[];
    int*   tok_s = (int*)(sm + TOK_OFF);
    const int tid = threadIdx.x, warp = tid >> 5, lane = tid & 31;
    const int pr = t & 1, cur = (t + 1) & 1;

    if (tid < BB) tok_s[tid] = (int)(~(unsigned)g_amax[pr][tid]);
    if (blockIdx.x == 0 && tid < BB) { g_amax[cur][tid] = 0ull; g_approx[cur][tid] = 0u; }
    __syncthreads();

    // gather + split emb[tok] into resident smem planes (once)
    __half* xhi = (__half*)(sm + XHI_OFF);
    __half* xlo = (__half*)(sm + XLO_OFF);
#pragma unroll
    for (int q = 0; q < 16; q++) {
        int i4 = tid + q * 256;
        int b = i4 >> 8, k = (i4 & 255) << 2;
        float4 v = *(const float4*)(emb + (size_t)tok_s[b] * EE + k);
        __half h0 = __float2half_rn(v.x), h1 = __float2half_rn(v.y);
        __half h2 = __float2half_rn(v.z), h3 = __float2half_rn(v.w);
        __half l0 = __float2half_rn(v.x - __half2float(h0));
        __half l1 = __float2half_rn(v.y - __half2float(h1));
        __half l2 = __float2half_rn(v.z - __half2float(h2));
        __half l3 = __float2half_rn(v.w - __half2float(h3));
        __half hi4[4] = {h0, h1, h2, h3};
        __half lo4[4] = {l0, l1, l2, l3};
        *(uint2*)(xhi + b * 1032 + k) = *(uint2*)hi4;
        *(uint2*)(xlo + b * 1032 + k) = *(uint2*)lo4;
    }
    __syncthreads();

    float acc[2][4] = {{0.f,0.f,0.f,0.f},{0.f,0.f,0.f,0.f}};
    k1_mainloop(sm, blockIdx.x, warp, lane, 0, acc);
    k1_reduce(sm, tid, warp, lane, acc);

    float* red = (float*)(sm + RED_OFF);
    if (tid < 64) {
        int u = tid >> 4, b = tid & 15;
        float gv[4];
#pragma unroll
        for (int g = 0; g < 4; g++) {
            int row = u * 4 + g;
            float s = g_pb[blockIdx.x * 16 + row] + g_gH[blockIdx.x * 256 + row * 16 + b];
#pragma unroll
            for (int w = 0; w < 8; w++) s += red[w * 272 + row * 17 + b];
            gv[g] = s;
        }
        int j = blockIdx.x * 4 + u;
        float si = 1.f / (1.f + expf(-gv[0]));
        float sf = 1.f / (1.f + expf(-gv[1]));
        float so = 1.f / (1.f + expf(-gv[3]));
        float cc = sf * g_c[b * HH + j] + si * tanhf(gv[2]);
        g_c[b * HH + j] = cc;
        float h = so * tanhf(cc);
        g_h[cur][b * HH + j] = h;
        __half hh = __float2half_rn(h);
        g_h16[b * HH + j] = hh;
        g_hlo[b * HH + j] = __float2half_rn(h - __half2float(hh));
    }
}

// ---------------------------------------------------------------------
// K2 v4 (R13, proven): W fragments via LDG.128, barrier-free mainloop.
__global__ void __launch_bounds__(K2_THREADS)
k_logits(int t, const float* __restrict__ Wlin, const float* __restrict__ blin,
         float* __restrict__ out) {
    extern __shared__ char sm[];
    __half* h_s   = (__half*)(sm + H_OFF);
    float*  log_s = (float*)(sm + LOG_OFF);
    float*  thr_s = (float*)(sm + THR_OFF);
    int*    cnt_s = (int*)(sm + CNT_OFF);
    int*    cand_s = (int*)(sm + CAND_OFF);

    const int tid = threadIdx.x, warp = tid >> 5, lane = tid & 31;
    const int cur = (t + 1) & 1;
    const int r = lane >> 2, q4 = lane & 3;

    const char* wbase = (const char*)g_WF
                      + (size_t)blockIdx.x * (NCHUNK * 16384) + (size_t)tid * 16;
    auto pf = [&](int c, uint4* wr) {
#pragma unroll
        for (int ks = 0; ks < 4; ks++)
            wr[ks] = *(const uint4*)(wbase + c * 16384 + ks * 4096);
    };

    uint4 wr0[4], wr1[4];
    pf(0, wr0);
    pf(1, wr1);
    cudaGridDependencySynchronize();
    cudaTriggerProgrammaticLaunchCompletion();

    if (tid == 0) *cnt_s = 0;
#pragma unroll
    for (int q = 0; q < 8; q++) {
        int i = tid + q * 256;
        int b = i >> 7, k8 = i & 127;
        float4 v = *(const float4*)(g_h16 + (size_t)b * HH + k8 * 8);
        *(float4*)(h_s + b * HPAD + k8 * 8) = v;
    }
    __syncthreads();

    float acc0[4] = {0.f, 0.f, 0.f, 0.f};
    float acc1[4] = {0.f, 0.f, 0.f, 0.f};

#pragma unroll
    for (int cc = 0; cc < NCHUNK; cc += 2) {
#pragma unroll
        for (int ks = 0; ks < 4; ks++) {
            int kg = cc * 64 + ks * 16 + q4 * 2;
            uint32_t b00 = *(const uint32_t*)(h_s + r * HPAD + kg);
            uint32_t b01 = *(const uint32_t*)(h_s + r * HPAD + kg + 8);
            uint32_t b10 = *(const uint32_t*)(h_s + (r + 8) * HPAD + kg);
            uint32_t b11 = *(const uint32_t*)(h_s + (r + 8) * HPAD + kg + 8);
            mma16816(acc0, wr0[ks].x, wr0[ks].y, wr0[ks].z, wr0[ks].w, b00, b01);
            mma16816(acc1, wr0[ks].x, wr0[ks].y, wr0[ks].z, wr0[ks].w, b10, b11);
        }
        if (cc + 2 < NCHUNK) pf(cc + 2, wr0);
#pragma unroll
        for (int ks = 0; ks < 4; ks++) {
            int kg = (cc + 1) * 64 + ks * 16 + q4 * 2;
            uint32_t b00 = *(const uint32_t*)(h_s + r * HPAD + kg);
            uint32_t b01 = *(const uint32_t*)(h_s + r * HPAD + kg + 8);
            uint32_t b10 = *(const uint32_t*)(h_s + (r + 8) * HPAD + kg);
            uint32_t b11 = *(const uint32_t*)(h_s + (r + 8) * HPAD + kg + 8);
            mma16816(acc0, wr1[ks].x, wr1[ks].y, wr1[ks].z, wr1[ks].w, b00, b01);
            mma16816(acc1, wr1[ks].x, wr1[ks].y, wr1[ks].z, wr1[ks].w, b10, b11);
        }
        if (cc + 3 < NCHUNK) pf(cc + 3, wr1);
    }

    {
        const int rbase = warp * 16 + r;
        const float bl0 = blin[blockIdx.x * K2_ROWS + rbase];
        const float bl1 = blin[blockIdx.x * K2_ROWS + rbase + 8];
        const int c0 = q4 * 2;
        log_s[rbase * LPAD + c0]           = acc0[0] + bl0;
        log_s[rbase * LPAD + c0 + 1]       = acc0[1] + bl0;
        log_s[(rbase + 8) * LPAD + c0]     = acc0[2] + bl1;
        log_s[(rbase + 8) * LPAD + c0 + 1] = acc0[3] + bl1;
        log_s[rbase * LPAD + c0 + 8]       = acc1[0] + bl0;
        log_s[rbase * LPAD + c0 + 9]       = acc1[1] + bl0;
        log_s[(rbase + 8) * LPAD + c0 + 8] = acc1[2] + bl1;
        log_s[(rbase + 8) * LPAD + c0 + 9] = acc1[3] + bl1;
    }
    __syncthreads();

#pragma unroll
    for (int i = 0; i < 8; i++) {
        int idx = tid + i * 256;
        int row = idx & 127, b = idx >> 7;
        out[(size_t)b * TT * VV + (size_t)t * VV + blockIdx.x * K2_ROWS + row] =
            log_s[row * LPAD + b];
    }

    {
        int b = 2 * warp + (lane >> 4);
        int l = lane & 15;
        float s = 0.f, m = -1e30f;
#pragma unroll
        for (int rr = 0; rr < 8; rr++) {
            float v = log_s[(l * 8 + rr) * LPAD + b];
            s += expf(v);
            m = fmaxf(m, v);
        }
#pragma unroll
        for (int off = 8; off; off >>= 1) {
            s += __shfl_xor_sync(0xFFFFFFFFu, s, off);
            m = fmaxf(m, __shfl_xor_sync(0xFFFFFFFFu, m, off));
        }
        if (l == 0) {
            g_pexp[t][b][blockIdx.x] = s;
            unsigned fm = ford(m);
            unsigned old = atomicMax(&g_approx[cur][b], fm);
            unsigned L = old > fm ? old : fm;
            thr_s[b] = funord(L) - TAU;
        }
    }
    __syncthreads();

#pragma unroll
    for (int i = 0; i < 8; i++) {
        int idx = tid + i * 256;
        int row = idx & 127, b = idx >> 7;
        if (log_s[row * LPAD + b] >= thr_s[b]) {
            int slot = atomicAdd(cnt_s, 1);
            if (slot < 128) cand_s[slot] = ((blockIdx.x * K2_ROWS + row) << 4) | b;
        }
    }
    __syncthreads();

    int n = *cnt_s; if (n > 128) n = 128;
    for (int e = warp; e < n; e += 8) {
        int pk = cand_s[e];
        int rr = pk >> 4, b = pk & 15;
        const float4* Wr = (const float4*)(Wlin + (size_t)rr * HH);
        const float4* hr = (const float4*)(g_h[cur] + b * HH);
        float acc = 0.f;
#pragma unroll
        for (int qq = 0; qq < 8; qq++) {
            float4 w = Wr[lane + qq * 32];
            float4 h = hr[lane + qq * 32];
            acc += w.x * h.x + w.y * h.y + w.z * h.z + w.w * h.w;
        }
#pragma unroll
        for (int off = 16; off; off >>= 1) acc += __shfl_xor_sync(0xFFFFFFFFu, acc, off);
        if (lane == 0) {
            float ex = acc + blin[rr];
            unsigned long long pkd =
                ((unsigned long long)ford(ex) << 32) | (unsigned)(~(unsigned)rr);
            atomicMax(&g_amax[cur][b], pkd);
        }
    }
}

// ---------------------------------------------------------------------
__global__ void k_final(float* __restrict__ out) {
    const int t = blockIdx.x >> 4;
    const int b = blockIdx.x & 15;
    __shared__ float red[256];
    float s = 0.f;
    for (int i = threadIdx.x; i < K2_BLOCKS; i += 256) s += g_pexp[t][b][i];
    red[threadIdx.x] = s;
    __syncthreads();
    for (int off = 128; off; off >>= 1) {
        if (threadIdx.x < off) red[threadIdx.x] += red[threadIdx.x + off];
        __syncthreads();
    }
    const float lse = logf(red[0]);
    float* p = out + (size_t)b * TT * VV + (size_t)t * VV;
    for (int i = threadIdx.x; i < VV / 4; i += 256) {
        float4 v = *(float4*)(p + i * 4);
        v.x -= lse; v.y -= lse; v.z -= lse; v.w -= lse;
        *(float4*)(p + i * 4) = v;
    }
}

__global__ void k_hc(float* __restrict__ out) {
    int i = blockIdx.x * blockDim.x + threadIdx.x;
    if (i < BB * HH) {
        out[(size_t)BB * TT * VV + i]           = g_h[0][i];
        out[(size_t)BB * TT * VV + BB * HH + i] = g_c[i];
    }
}

// ---------------------------------------------------------------------
extern "C" void kernel_launch(void* const* d_in, const int* in_sizes, int n_in,
                              void* d_out, int out_size) {
    const float* h0   = (const float*)d_in[1];
    const float* c0   = (const float*)d_in[2];
    const float* emb  = (const float*)d_in[3];
    const float* Wih  = (const float*)d_in[4];
    const float* Whh  = (const float*)d_in[5];
    const float* bih  = (const float*)d_in[6];
    const float* bhh  = (const float*)d_in[7];
    const float* Wlin = (const float*)d_in[8];
    const float* blin = (const float*)d_in[9];
    float* out = (float*)d_out;

    cudaFuncSetAttribute(k_lstmX,  cudaFuncAttributeMaxDynamicSharedMemorySize, K1_SMEM);
    cudaFuncSetAttribute(k_gemmH,  cudaFuncAttributeMaxDynamicSharedMemorySize, K1_SMEM);
    cudaFuncSetAttribute(k_logits, cudaFuncAttributeMaxDynamicSharedMemorySize, K2_SMEM);

    cudaLaunchAttribute pdl[1];
    pdl[0].id = cudaLaunchAttributeProgrammaticStreamSerialization;
    pdl[0].val.programmaticStreamSerializationAllowed = 1;

    k_init<<<(BB * HH + 255) / 256, 256>>>(h0, c0, bih, bhh);
    k_cvtF<<<(K2_BLOCKS * NCHUNK * 4 * 256) / 256, 256>>>(Wlin);
    k_cvt2F<<<(K1_BLOCKS * 4096) / 256, 256>>>(Wih, Whh);

    k_gemmH<<<K1_BLOCKS, K1_THREADS, K1_SMEM>>>(0);

    for (int t = 0; t < TT; t++) {
        k_lstmX<<<K1_BLOCKS, K1_THREADS, K1_SMEM>>>(t, emb);

        if (t < TT - 1) {
            cudaLaunchConfig_t cfg = {};
            cfg.gridDim = dim3(K1_BLOCKS); cfg.blockDim = dim3(K1_THREADS);
            cfg.dynamicSmemBytes = K1_SMEM; cfg.stream = 0;
            cfg.attrs = pdl; cfg.numAttrs = 1;
            cudaLaunchKernelEx(&cfg, k_gemmH, t + 1);
        }
        {
            cudaLaunchConfig_t cfg = {};
            cfg.gridDim = dim3(K2_BLOCKS); cfg.blockDim = dim3(K2_THREADS);
            cfg.dynamicSmemBytes = K2_SMEM; cfg.stream = 0;
            cfg.attrs = pdl; cfg.numAttrs = 1;
            cudaLaunchKernelEx(&cfg, k_logits, t, Wlin, blin, out);
        }
    }
    k_final<<<TT * BB, 256>>>(out);
    k_hc<<<(BB * HH + 255) / 256, 256>>>(out);
}

// round 15
// speedup vs baseline: 1.0601x; 1.0601x over previous
#include <cuda_runtime.h>
#include <cuda_fp16.h>
#include <math.h>
#include <stdint.h>

#define BB 16
#define TT 128
#define HH 1024
#define EE 1024
#define VV 32000
#define KK 2048

// ---- K1 (HMMA LSTM halves) ----
#define K1_BLOCKS 256
#define K1_THREADS 256
#define XHI_OFF  0          // 16*1032*2 = 33024
#define XLO_OFF  33024
#define RED_OFF  66048      // 8*16*17*4 = 8704
#define TOK_OFF  74752
#define K1_SMEM  74816

// ---- K2 (logits) ----
#define K2_ROWS   128
#define K2_BLOCKS (VV / K2_ROWS)     // 250
#define K2_THREADS 256
#define NCHUNK 16
#define TAU 0.05f
#define HPAD 1032
#define LPAD 17
#define H_OFF    0
#define LOG_OFF  33024
#define THR_OFF  41728
#define CNT_OFF  41792
#define CAND_OFF 41808
#define K2_SMEM  42320

// -------- persistent scratch --------
__device__ float  g_h[2][BB * HH];
__device__ float  g_c[BB * HH];
__device__ __half g_h16[BB * HH];
__device__ __half g_hlo[BB * HH];
__device__ __align__(128) __half g_WF[(size_t)VV * HH];
__device__ __align__(128) __half g_WhiF[(size_t)4 * HH * KK];
__device__ __align__(128) __half g_WloF[(size_t)4 * HH * KK];
__device__ float  g_gH[K1_BLOCKS * 256];
__device__ float  g_pb[4 * HH];
__device__ unsigned long long g_amax[2][BB];
__device__ unsigned g_approx[2][BB];
__device__ float  g_pexp[TT][BB][K2_BLOCKS];

// ---------------- helpers ----------------
__device__ __forceinline__ unsigned ford(float f) {
    unsigned u = __float_as_uint(f);
    return (u & 0x80000000u) ? ~u : (u | 0x80000000u);
}
__device__ __forceinline__ float funord(unsigned v) {
    unsigned bits = (v & 0x80000000u) ? (v ^ 0x80000000u) : ~v;
    return __uint_as_float(bits);
}
__device__ __forceinline__ void mma16816(float* c, uint32_t a0, uint32_t a1,
                                         uint32_t a2, uint32_t a3,
                                         uint32_t b0, uint32_t b1) {
    asm volatile(
        "mma.sync.aligned.m16n8k16.row.col.f32.f16.f16.f32 "
        "{%0,%1,%2,%3}, {%4,%5,%6,%7}, {%8,%9}, {%0,%1,%2,%3};"
        : "+f"(c[0]), "+f"(c[1]), "+f"(c[2]), "+f"(c[3])
        : "r"(a0), "r"(a1), "r"(a2), "r"(a3), "r"(b0), "r"(b1));
}

// ---------------------------------------------------------------------
__global__ void k_init(const float* __restrict__ h0, const float* __restrict__ c0,
                       const float* __restrict__ bih, const float* __restrict__ bhh) {
    int i = blockIdx.x * blockDim.x + threadIdx.x;
    if (i < BB * HH) {
        float h = h0[i];
        g_h[0][i] = h;
        g_c[i]    = c0[i];
        __half hh = __float2half_rn(h);
        g_h16[i] = hh;
        g_hlo[i] = __float2half_rn(h - __half2float(hh));
    }
    if (i < BB) g_amax[0][i] = (unsigned long long)(~1u);   // SOS = 1
    if (i < 4 * HH) {
        int j = i >> 2, g = i & 3;
        int orig = g * HH + j;
        g_pb[i] = bih[orig] + bhh[orig];
    }
}

// W_lin fp32 -> fragment-packed fp16 (proven R13 layout)
__global__ void k_cvtF(const float* __restrict__ W) {
    unsigned u = blockIdx.x * 256 + threadIdx.x;
    int blk = u >> 14;
    int rem = u & 16383;
    int c   = rem >> 10;
    int rem2 = rem & 1023;
    int ks  = rem2 >> 8;
    int tt  = rem2 & 255;
    int warp = tt >> 5, lane = tt & 31;
    int r = lane >> 2, q4 = lane & 3;
    int row0 = blk * 128 + warp * 16 + r;
    int k = c * 64 + ks * 16 + q4 * 2;
    const float* p0 = W + (size_t)row0 * HH + k;
    const float* p1 = W + (size_t)(row0 + 8) * HH + k;
    float2 xa = *(const float2*)p0;
    float2 xb = *(const float2*)p1;
    float2 xc = *(const float2*)(p0 + 8);
    float2 xd = *(const float2*)(p1 + 8);
    __half2 ha = __floats2half2_rn(xa.x, xa.y);
    __half2 hb = __floats2half2_rn(xb.x, xb.y);
    __half2 hc = __floats2half2_rn(xc.x, xc.y);
    __half2 hd = __floats2half2_rn(xd.x, xd.y);
    uint4 o;
    o.x = *(uint32_t*)&ha; o.y = *(uint32_t*)&hb;
    o.z = *(uint32_t*)&hc; o.w = *(uint32_t*)&hd;
    *(uint4*)((char*)g_WF + (size_t)u * 16) = o;
}

// Gate weights -> split fp16, fragment-packed (R14 layout, bitwise-validated)
__device__ __forceinline__ float ld_gate(const float* Wih, const float* Whh, int nr, int k) {
    int j = nr >> 2, g = nr & 3;
    int orig = g * HH + j;
    return (k < HH) ? Wih[(size_t)orig * HH + k] : Whh[(size_t)orig * HH + (k - HH)];
}
__global__ void k_cvt2F(const float* __restrict__ Wih, const float* __restrict__ Whh) {
    unsigned u = blockIdx.x * 256 + threadIdx.x;
    int blk = u >> 12;
    int rem = u & 4095;
    int c   = rem >> 9;
    int rem2 = rem & 511;
    int w   = rem2 >> 6;
    int rem3 = rem2 & 63;
    int s   = rem3 >> 5;
    int lane = rem3 & 31;
    int r = lane >> 2, q4 = lane & 3;
    int row0 = blk * 16 + r, row1 = row0 + 8;
    int k = c * 256 + w * 32 + s * 16 + q4 * 2;
    float v[8];
    v[0] = ld_gate(Wih, Whh, row0, k);     v[1] = ld_gate(Wih, Whh, row0, k + 1);
    v[2] = ld_gate(Wih, Whh, row1, k);     v[3] = ld_gate(Wih, Whh, row1, k + 1);
    v[4] = ld_gate(Wih, Whh, row0, k + 8); v[5] = ld_gate(Wih, Whh, row0, k + 9);
    v[6] = ld_gate(Wih, Whh, row1, k + 8); v[7] = ld_gate(Wih, Whh, row1, k + 9);
    __half hi[8], lo[8];
#pragma unroll
    for (int q = 0; q < 8; q++) {
        __half h = __float2half_rn(v[q]);
        hi[q] = h;
        lo[q] = __float2half_rn(v[q] - __half2float(h));
    }
    *(uint4*)((char*)g_WhiF + (size_t)u * 16) = *(uint4*)hi;
    *(uint4*)((char*)g_WloF + (size_t)u * 16) = *(uint4*)lo;
}

// ---------------------------------------------------------------------
// Full-depth W fragment load: 16 uint4 per thread in one MLP-16 burst.
__device__ __forceinline__ void k1_load_w(int blkid, int warp, int lane, int cbase,
                                          uint4 wh[4][2], uint4 wl[4][2]) {
    const size_t fbase = (((size_t)blkid * 8) * 512 + (size_t)warp * 64 + lane) * 16;
    const char* fhi = (const char*)g_WhiF + fbase;
    const char* flo = (const char*)g_WloF + fbase;
#pragma unroll
    for (int c = 0; c < 4; c++)
#pragma unroll
        for (int s = 0; s < 2; s++) {
            wh[c][s] = *(const uint4*)(fhi + (size_t)(cbase + c) * 8192 + s * 512);
            wl[c][s] = *(const uint4*)(flo + (size_t)(cbase + c) * 8192 + s * 512);
        }
}

// MMA mainloop from preloaded registers; x planes resident in smem.
__device__ __forceinline__ void k1_mma(char* sm, int warp, int lane,
                                       const uint4 wh[4][2], const uint4 wl[4][2],
                                       float acc[2][4]) {
    const int r = lane >> 2, q4 = lane & 3;
    const __half* xhi = (const __half*)(sm + XHI_OFF);
    const __half* xlo = (const __half*)(sm + XLO_OFF);
#pragma unroll
    for (int c = 0; c < 4; c++) {
#pragma unroll
        for (int s = 0; s < 2; s++) {
            int kg = c * 256 + warp * 32 + s * 16 + q4 * 2;
#pragma unroll
            for (int nbi = 0; nbi < 2; nbi++) {
                const __half* bx = xhi + (nbi * 8 + r) * 1032;
                const __half* by = xlo + (nbi * 8 + r) * 1032;
                uint32_t bh0 = *(const uint32_t*)(bx + kg);
                uint32_t bh1 = *(const uint32_t*)(bx + kg + 8);
                uint32_t bl0 = *(const uint32_t*)(by + kg);
                uint32_t bl1 = *(const uint32_t*)(by + kg + 8);
                mma16816(acc[nbi], wh[c][s].x, wh[c][s].y, wh[c][s].z, wh[c][s].w, bh0, bh1);
                mma16816(acc[nbi], wh[c][s].x, wh[c][s].y, wh[c][s].z, wh[c][s].w, bl0, bl1);
                mma16816(acc[nbi], wl[c][s].x, wl[c][s].y, wl[c][s].z, wl[c][s].w, bh0, bh1);
            }
        }
    }
}

__device__ __forceinline__ void k1_reduce(char* sm, int warp, int lane, float acc[2][4]) {
    float* red = (float*)(sm + RED_OFF);
    const int r = lane >> 2, q4 = lane & 3;
#pragma unroll
    for (int nbi = 0; nbi < 2; nbi++) {
        int col = nbi * 8 + q4 * 2;
        red[warp * 272 + r * 17 + col]           = acc[nbi][0];
        red[warp * 272 + r * 17 + col + 1]       = acc[nbi][1];
        red[warp * 272 + (r + 8) * 17 + col]     = acc[nbi][2];
        red[warp * 272 + (r + 8) * 17 + col + 1] = acc[nbi][3];
    }
    __syncthreads();
}

// ---------------------------------------------------------------------
// k_gemmH: Whh_split @ h_t. W fully in registers BEFORE grid-sync (PDL).
__global__ void __launch_bounds__(K1_THREADS)
k_gemmH(int t) {
    extern __shared__ char sm[];
    const int tid = threadIdx.x, warp = tid >> 5, lane = tid & 31;

    uint4 wh[4][2], wl[4][2];
    k1_load_w(blockIdx.x, warp, lane, 4, wh, wl);   // h-independent burst
    cudaGridDependencySynchronize();
    cudaTriggerProgrammaticLaunchCompletion();

    __half* xhi = (__half*)(sm + XHI_OFF);
    __half* xlo = (__half*)(sm + XLO_OFF);
#pragma unroll
    for (int q = 0; q < 8; q++) {
        int i = tid + q * 256;
        int b = i >> 7, k8 = i & 127;
        *(float4*)(xhi + b * 1032 + k8 * 8) = *(const float4*)(g_h16 + b * HH + k8 * 8);
        *(float4*)(xlo + b * 1032 + k8 * 8) = *(const float4*)(g_hlo + b * HH + k8 * 8);
    }
    __syncthreads();

    float acc[2][4] = {{0.f,0.f,0.f,0.f},{0.f,0.f,0.f,0.f}};
    k1_mma(sm, warp, lane, wh, wl, acc);
    k1_reduce(sm, warp, lane, acc);

    float* red = (float*)(sm + RED_OFF);
    if (tid < 64) {
        int u = tid >> 4, b = tid & 15;
#pragma unroll
        for (int g = 0; g < 4; g++) {
            int row = u * 4 + g;
            float s = 0.f;
#pragma unroll
            for (int w = 0; w < 8; w++) s += red[w * 272 + row * 17 + b];
            g_gH[blockIdx.x * 256 + row * 16 + b] = s;
        }
    }
}

// ---------------------------------------------------------------------
// k_lstmX: Wih_split @ emb[tok] + g_gH + bias; pointwise (plain launch).
// W burst issues first; latency overlaps token read + x build.
__global__ void __launch_bounds__(K1_THREADS)
k_lstmX(int t, const float* __restrict__ emb) {
    extern __shared__ char sm[];
    int*   tok_s = (int*)(sm + TOK_OFF);
    const int tid = threadIdx.x, warp = tid >> 5, lane = tid & 31;
    const int pr = t & 1, cur = (t + 1) & 1;

    uint4 wh[4][2], wl[4][2];
    k1_load_w(blockIdx.x, warp, lane, 0, wh, wl);

    if (tid < BB) tok_s[tid] = (int)(~(unsigned)g_amax[pr][tid]);
    if (blockIdx.x == 0 && tid < BB) { g_amax[cur][tid] = 0ull; g_approx[cur][tid] = 0u; }
    __syncthreads();

    __half* xhi = (__half*)(sm + XHI_OFF);
    __half* xlo = (__half*)(sm + XLO_OFF);
#pragma unroll
    for (int q = 0; q < 16; q++) {
        int i4 = tid + q * 256;
        int b = i4 >> 8, k = (i4 & 255) << 2;
        float4 v = *(const float4*)(emb + (size_t)tok_s[b] * EE + k);
        __half h0 = __float2half_rn(v.x), h1 = __float2half_rn(v.y);
        __half h2 = __float2half_rn(v.z), h3 = __float2half_rn(v.w);
        __half l0 = __float2half_rn(v.x - __half2float(h0));
        __half l1 = __float2half_rn(v.y - __half2float(h1));
        __half l2 = __float2half_rn(v.z - __half2float(h2));
        __half l3 = __float2half_rn(v.w - __half2float(h3));
        __half hi4[4] = {h0, h1, h2, h3};
        __half lo4[4] = {l0, l1, l2, l3};
        *(uint2*)(xhi + b * 1032 + k) = *(uint2*)hi4;
        *(uint2*)(xlo + b * 1032 + k) = *(uint2*)lo4;
    }
    __syncthreads();

    float acc[2][4] = {{0.f,0.f,0.f,0.f},{0.f,0.f,0.f,0.f}};
    k1_mma(sm, warp, lane, wh, wl, acc);
    k1_reduce(sm, warp, lane, acc);

    float* red = (float*)(sm + RED_OFF);
    if (tid < 64) {
        int u = tid >> 4, b = tid & 15;
        float gv[4];
#pragma unroll
        for (int g = 0; g < 4; g++) {
            int row = u * 4 + g;
            float s = g_pb[blockIdx.x * 16 + row] + g_gH[blockIdx.x * 256 + row * 16 + b];
#pragma unroll
            for (int w = 0; w < 8; w++) s += red[w * 272 + row * 17 + b];
            gv[g] = s;
        }
        int j = blockIdx.x * 4 + u;
        float si = 1.f / (1.f + expf(-gv[0]));
        float sf = 1.f / (1.f + expf(-gv[1]));
        float so = 1.f / (1.f + expf(-gv[3]));
        float cc = sf * g_c[b * HH + j] + si * tanhf(gv[2]);
        g_c[b * HH + j] = cc;
        float h = so * tanhf(cc);
        g_h[cur][b * HH + j] = h;
        __half hh = __float2half_rn(h);
        g_h16[b * HH + j] = hh;
        g_hlo[b * HH + j] = __float2half_rn(h - __half2float(hh));
    }
}

// ---------------------------------------------------------------------
// K2 v4 (R13, proven): W fragments via LDG.128, barrier-free mainloop.
__global__ void __launch_bounds__(K2_THREADS)
k_logits(int t, const float* __restrict__ Wlin, const float* __restrict__ blin,
         float* __restrict__ out) {
    extern __shared__ char sm[];
    __half* h_s   = (__half*)(sm + H_OFF);
    float*  log_s = (float*)(sm + LOG_OFF);
    float*  thr_s = (float*)(sm + THR_OFF);
    int*    cnt_s = (int*)(sm + CNT_OFF);
    int*    cand_s = (int*)(sm + CAND_OFF);

    const int tid = threadIdx.x, warp = tid >> 5, lane = tid & 31;
    const int cur = (t + 1) & 1;
    const int r = lane >> 2, q4 = lane & 3;

    const char* wbase = (const char*)g_WF
                      + (size_t)blockIdx.x * (NCHUNK * 16384) + (size_t)tid * 16;
    auto pf = [&](int c, uint4* wr) {
#pragma unroll
        for (int ks = 0; ks < 4; ks++)
            wr[ks] = *(const uint4*)(wbase + c * 16384 + ks * 4096);
    };

    uint4 wr0[4], wr1[4];
    pf(0, wr0);
    pf(1, wr1);
    cudaGridDependencySynchronize();
    cudaTriggerProgrammaticLaunchCompletion();

    if (tid == 0) *cnt_s = 0;
#pragma unroll
    for (int q = 0; q < 8; q++) {
        int i = tid + q * 256;
        int b = i >> 7, k8 = i & 127;
        float4 v = *(const float4*)(g_h16 + (size_t)b * HH + k8 * 8);
        *(float4*)(h_s + b * HPAD + k8 * 8) = v;
    }
    __syncthreads();

    float acc0[4] = {0.f, 0.f, 0.f, 0.f};
    float acc1[4] = {0.f, 0.f, 0.f, 0.f};

#pragma unroll
    for (int cc = 0; cc < NCHUNK; cc += 2) {
#pragma unroll
        for (int ks = 0; ks < 4; ks++) {
            int kg = cc * 64 + ks * 16 + q4 * 2;
            uint32_t b00 = *(const uint32_t*)(h_s + r * HPAD + kg);
            uint32_t b01 = *(const uint32_t*)(h_s + r * HPAD + kg + 8);
            uint32_t b10 = *(const uint32_t*)(h_s + (r + 8) * HPAD + kg);
            uint32_t b11 = *(const uint32_t*)(h_s + (r + 8) * HPAD + kg + 8);
            mma16816(acc0, wr0[ks].x, wr0[ks].y, wr0[ks].z, wr0[ks].w, b00, b01);
            mma16816(acc1, wr0[ks].x, wr0[ks].y, wr0[ks].z, wr0[ks].w, b10, b11);
        }
        if (cc + 2 < NCHUNK) pf(cc + 2, wr0);
#pragma unroll
        for (int ks = 0; ks < 4; ks++) {
            int kg = (cc + 1) * 64 + ks * 16 + q4 * 2;
            uint32_t b00 = *(const uint32_t*)(h_s + r * HPAD + kg);
            uint32_t b01 = *(const uint32_t*)(h_s + r * HPAD + kg + 8);
            uint32_t b10 = *(const uint32_t*)(h_s + (r + 8) * HPAD + kg);
            uint32_t b11 = *(const uint32_t*)(h_s + (r + 8) * HPAD + kg + 8);
            mma16816(acc0, wr1[ks].x, wr1[ks].y, wr1[ks].z, wr1[ks].w, b00, b01);
            mma16816(acc1, wr1[ks].x, wr1[ks].y, wr1[ks].z, wr1[ks].w, b10, b11);
        }
        if (cc + 3 < NCHUNK) pf(cc + 3, wr1);
    }

    {
        const int rbase = warp * 16 + r;
        const float bl0 = blin[blockIdx.x * K2_ROWS + rbase];
        const float bl1 = blin[blockIdx.x * K2_ROWS + rbase + 8];
        const int c0 = q4 * 2;
        log_s[rbase * LPAD + c0]           = acc0[0] + bl0;
        log_s[rbase * LPAD + c0 + 1]       = acc0[1] + bl0;
        log_s[(rbase + 8) * LPAD + c0]     = acc0[2] + bl1;
        log_s[(rbase + 8) * LPAD + c0 + 1] = acc0[3] + bl1;
        log_s[rbase * LPAD + c0 + 8]       = acc1[0] + bl0;
        log_s[rbase * LPAD + c0 + 9]       = acc1[1] + bl0;
        log_s[(rbase + 8) * LPAD + c0 + 8] = acc1[2] + bl1;
        log_s[(rbase + 8) * LPAD + c0 + 9] = acc1[3] + bl1;
    }
    __syncthreads();

#pragma unroll
    for (int i = 0; i < 8; i++) {
        int idx = tid + i * 256;
        int row = idx & 127, b = idx >> 7;
        out[(size_t)b * TT * VV + (size_t)t * VV + blockIdx.x * K2_ROWS + row] =
            log_s[row * LPAD + b];
    }

    {
        int b = 2 * warp + (lane >> 4);
        int l = lane & 15;
        float s = 0.f, m = -1e30f;
#pragma unroll
        for (int rr = 0; rr < 8; rr++) {
            float v = log_s[(l * 8 + rr) * LPAD + b];
            s += expf(v);
            m = fmaxf(m, v);
        }
#pragma unroll
        for (int off = 8; off; off >>= 1) {
            s += __shfl_xor_sync(0xFFFFFFFFu, s, off);
            m = fmaxf(m, __shfl_xor_sync(0xFFFFFFFFu, m, off));
        }
        if (l == 0) {
            g_pexp[t][b][blockIdx.x] = s;
            unsigned fm = ford(m);
            unsigned old = atomicMax(&g_approx[cur][b], fm);
            unsigned L = old > fm ? old : fm;
            thr_s[b] = funord(L) - TAU;
        }
    }
    __syncthreads();

#pragma unroll
    for (int i = 0; i < 8; i++) {
        int idx = tid + i * 256;
        int row = idx & 127, b = idx >> 7;
        if (log_s[row * LPAD + b] >= thr_s[b]) {
            int slot = atomicAdd(cnt_s, 1);
            if (slot < 128) cand_s[slot] = ((blockIdx.x * K2_ROWS + row) << 4) | b;
        }
    }
    __syncthreads();

    int n = *cnt_s; if (n > 128) n = 128;
    for (int e = warp; e < n; e += 8) {
        int pk = cand_s[e];
        int rr = pk >> 4, b = pk & 15;
        const float4* Wr = (const float4*)(Wlin + (size_t)rr * HH);
        const float4* hr = (const float4*)(g_h[cur] + b * HH);
        float acc = 0.f;
#pragma unroll
        for (int qq = 0; qq < 8; qq++) {
            float4 w = Wr[lane + qq * 32];
            float4 h = hr[lane + qq * 32];
            acc += w.x * h.x + w.y * h.y + w.z * h.z + w.w * h.w;
        }
#pragma unroll
        for (int off = 16; off; off >>= 1) acc += __shfl_xor_sync(0xFFFFFFFFu, acc, off);
        if (lane == 0) {
            float ex = acc + blin[rr];
            unsigned long long pkd =
                ((unsigned long long)ford(ex) << 32) | (unsigned)(~(unsigned)rr);
            atomicMax(&g_amax[cur][b], pkd);
        }
    }
}

// ---------------------------------------------------------------------
__global__ void k_final(float* __restrict__ out) {
    const int t = blockIdx.x >> 4;
    const int b = blockIdx.x & 15;
    __shared__ float red[256];
    float s = 0.f;
    for (int i = threadIdx.x; i < K2_BLOCKS; i += 256) s += g_pexp[t][b][i];
    red[threadIdx.x] = s;
    __syncthreads();
    for (int off = 128; off; off >>= 1) {
        if (threadIdx.x < off) red[threadIdx.x] += red[threadIdx.x + off];
        __syncthreads();
    }
    const float lse = logf(red[0]);
    float* p = out + (size_t)b * TT * VV + (size_t)t * VV;
    for (int i = threadIdx.x; i < VV / 4; i += 256) {
        float4 v = *(float4*)(p + i * 4);
        v.x -= lse; v.y -= lse; v.z -= lse; v.w -= lse;
        *(float4*)(p + i * 4) = v;
    }
}

__global__ void k_hc(float* __restrict__ out) {
    int i = blockIdx.x * blockDim.x + threadIdx.x;
    if (i < BB * HH) {
        out[(size_t)BB * TT * VV + i]           = g_h[0][i];
        out[(size_t)BB * TT * VV + BB * HH + i] = g_c[i];
    }
}

// ---------------------------------------------------------------------
extern "C" void kernel_launch(void* const* d_in, const int* in_sizes, int n_in,
                              void* d_out, int out_size) {
    const float* h0   = (const float*)d_in[1];
    const float* c0   = (const float*)d_in[2];
    const float* emb  = (const float*)d_in[3];
    const float* Wih  = (const float*)d_in[4];
    const float* Whh  = (const float*)d_in[5];
    const float* bih  = (const float*)d_in[6];
    const float* bhh  = (const float*)d_in[7];
    const float* Wlin = (const float*)d_in[8];
    const float* blin = (const float*)d_in[9];
    float* out = (float*)d_out;

    cudaFuncSetAttribute(k_lstmX,  cudaFuncAttributeMaxDynamicSharedMemorySize, K1_SMEM);
    cudaFuncSetAttribute(k_gemmH,  cudaFuncAttributeMaxDynamicSharedMemorySize, K1_SMEM);
    cudaFuncSetAttribute(k_logits, cudaFuncAttributeMaxDynamicSharedMemorySize, K2_SMEM);

    cudaLaunchAttribute pdl[1];
    pdl[0].id = cudaLaunchAttributeProgrammaticStreamSerialization;
    pdl[0].val.programmaticStreamSerializationAllowed = 1;

    k_init<<<(BB * HH + 255) / 256, 256>>>(h0, c0, bih, bhh);
    k_cvtF<<<(K2_BLOCKS * NCHUNK * 4 * 256) / 256, 256>>>(Wlin);
    k_cvt2F<<<(K1_BLOCKS * 4096) / 256, 256>>>(Wih, Whh);

    k_gemmH<<<K1_BLOCKS, K1_THREADS, K1_SMEM>>>(0);

    for (int t = 0; t < TT; t++) {
        k_lstmX<<<K1_BLOCKS, K1_THREADS, K1_SMEM>>>(t, emb);

        if (t < TT - 1) {
            cudaLaunchConfig_t cfg = {};
            cfg.gridDim = dim3(K1_BLOCKS); cfg.blockDim = dim3(K1_THREADS);
            cfg.dynamicSmemBytes = K1_SMEM; cfg.stream = 0;
            cfg.attrs = pdl; cfg.numAttrs = 1;
            cudaLaunchKernelEx(&cfg, k_gemmH, t + 1);
        }
        {
            cudaLaunchConfig_t cfg = {};
            cfg.gridDim = dim3(K2_BLOCKS); cfg.blockDim = dim3(K2_THREADS);
            cfg.dynamicSmemBytes = K2_SMEM; cfg.stream = 0;
            cfg.attrs = pdl; cfg.numAttrs = 1;
            cudaLaunchKernelEx(&cfg, k_logits, t, Wlin, blin, out);
        }
    }
    k_final<<<TT * BB, 256>>>(out);
    k_hc<<<(BB * HH + 255) / 256, 256>>>(out);
}